// round 17
// baseline (speedup 1.0000x reference)
#include <cuda_runtime.h>
#include <cuda_fp16.h>
#include <stdint.h>

#define NN    50000
#define HID   128
#define NREL  3
#define EMAX  800000

// ---------------- scratch (device globals; 16B-aligned) ----------------------
__device__ __align__(16) float  g_h  [(size_t)NN * HID];       // current features (fp32)
__device__ __align__(16) __half g_hw [NREL][(size_t)NN * HID]; // (h @ w[r]) * dis[r], fp16
__device__ __align__(16) int    g_deg[NREL][NN];
__device__ __align__(16) int    g_off[NREL][NN + 1];           // CSR row offsets
__device__ __align__(16) int    g_cur[NREL][NN];               // fill cursors
__device__ __align__(16) int    g_csr[NREL][EMAX];             // src sorted by dst
__device__ int g_scan_done;                                    // scan completion flag
__device__ int g_done1[782];   // gather-1 completion per 64-node tile
__device__ int g_done2[391];   // gather-2 completion per 128-node tile

// ---------------- fp32 GEMM body (embedder + final linear) --------------------
template <int BM, int BN, int BK, int TM, int TN, int MODE>
__device__ __forceinline__ void sgemm_body(const float* __restrict__ Aext,
                                           const float* __restrict__ Bmat,
                                           const float* __restrict__ bias,
                                           float* __restrict__ Cext,
                                           int M, int K, int tilex) {
    const float* A = (MODE == 0) ? Aext : g_h;
    const float* B = Bmat;

    __shared__ __align__(16) float As[BK][BM + 4];
    __shared__ __align__(16) float Bs[BK][BN];

    const int tid  = threadIdx.x;
    constexpr int TC = BN / TN;
    const int trow = tid / TC;
    const int tcol = tid % TC;
    const int rowBase = tilex * BM;

    float acc[TM][TN];
#pragma unroll
    for (int i = 0; i < TM; i++)
#pragma unroll
        for (int j = 0; j < TN; j++) acc[i][j] = 0.f;

    constexpr int ACNT = BM * BK / 4;
    constexpr int BCNT = BK * BN / 4;
    constexpr int AF4  = (ACNT + 255) / 256;
    constexpr int BF4  = (BCNT + 255) / 256;
    float4 va[AF4], vb[BF4];

    const int ntiles = K / BK;

    auto fetch = [&](int k0) {
#pragma unroll
        for (int v = 0; v < AF4; v++) {
            int g = tid + v * 256;
            if ((ACNT % 256 == 0) || g < ACNT) {
                int row = g / (BK / 4), c4 = g % (BK / 4);
                int gr = rowBase + row; if (gr >= M) gr = M - 1;
                va[v] = *(const float4*)&A[(size_t)gr * K + k0 + c4 * 4];
            }
        }
#pragma unroll
        for (int v = 0; v < BF4; v++) {
            int g = tid + v * 256;
            if ((BCNT % 256 == 0) || g < BCNT) {
                int row = g / (BN / 4), c4 = g % (BN / 4);
                vb[v] = *(const float4*)&B[(size_t)(k0 + row) * BN + c4 * 4];
            }
        }
    };
    auto commit = [&]() {
#pragma unroll
        for (int v = 0; v < AF4; v++) {
            int g = tid + v * 256;
            if ((ACNT % 256 == 0) || g < ACNT) {
                int row = g / (BK / 4), c4 = g % (BK / 4);
                As[c4 * 4 + 0][row] = va[v].x;
                As[c4 * 4 + 1][row] = va[v].y;
                As[c4 * 4 + 2][row] = va[v].z;
                As[c4 * 4 + 3][row] = va[v].w;
            }
        }
#pragma unroll
        for (int v = 0; v < BF4; v++) {
            int g = tid + v * 256;
            if ((BCNT % 256 == 0) || g < BCNT) {
                int row = g / (BN / 4), c4 = g % (BN / 4);
                *(float4*)&Bs[row][c4 * 4] = vb[v];
            }
        }
    };

    fetch(0);
    commit();
    __syncthreads();

    for (int t = 0; t < ntiles; t++) {
        if (t + 1 < ntiles) fetch((t + 1) * BK);
#pragma unroll
        for (int kk = 0; kk < BK; kk++) {
            float a[TM], b[TN];
#pragma unroll
            for (int i = 0; i < TM; i++) a[i] = As[kk][trow * TM + i];
#pragma unroll
            for (int j = 0; j < TN; j++) b[j] = Bs[kk][tcol * TN + j];
#pragma unroll
            for (int i = 0; i < TM; i++)
#pragma unroll
                for (int j = 0; j < TN; j++)
                    acc[i][j] = fmaf(a[i], b[j], acc[i][j]);
        }
        __syncthreads();
        if (t + 1 < ntiles) {
            commit();
            __syncthreads();
        }
    }

#pragma unroll
    for (int i = 0; i < TM; i++) {
        int gr = rowBase + trow * TM + i;
        if (gr >= M) continue;
#pragma unroll
        for (int j = 0; j < TN; j++) {
            int gc = tcol * TN + j;
            float v = acc[i][j];
            if (MODE == 0) {
                g_h[(size_t)gr * BN + gc] = fmaxf(v + bias[gc], 0.f);
            } else {
                Cext[(size_t)gr * BN + gc] = v + bias[gc];
            }
        }
    }
}

// ---------------- half2 HFMA2 GEMM body (relation GEMMs) ----------------------
__device__ __forceinline__ void hgemm_body(const float* __restrict__ Bmat,
                                           int r, int tilex) {
    constexpr int BM = 64, BN = 128, BK = 16;
    const float* B = Bmat + (size_t)r * HID * BN;

    __shared__ __align__(16) __half2 As[BK][BM + 4];   // splat {a,a} per element
    __shared__ __align__(16) __half2 Bs[BK][BN / 2];   // col pairs

    const int tid  = threadIdx.x;
    const int trow = tid / 16;
    const int tcol = tid % 16;
    const int rowBase = tilex * BM;

    float acc[4][8];
#pragma unroll
    for (int i = 0; i < 4; i++)
#pragma unroll
        for (int j = 0; j < 8; j++) acc[i][j] = 0.f;

    float4 va, vb[2];
    auto fetch = [&](int k0) {
        {
            int row = tid / 4, c4 = tid % 4;
            int gr = rowBase + row; if (gr >= NN) gr = NN - 1;
            va = *(const float4*)&g_h[(size_t)gr * HID + k0 + c4 * 4];
        }
#pragma unroll
        for (int v = 0; v < 2; v++) {
            int g = tid + v * 256;
            int row = g / 32, c4 = g % 32;
            vb[v] = *(const float4*)&B[(size_t)(k0 + row) * BN + c4 * 4];
        }
    };
    auto commit = [&]() {
        {
            int row = tid / 4, c4 = tid % 4;
            As[c4 * 4 + 0][row] = __float2half2_rn(va.x);
            As[c4 * 4 + 1][row] = __float2half2_rn(va.y);
            As[c4 * 4 + 2][row] = __float2half2_rn(va.z);
            As[c4 * 4 + 3][row] = __float2half2_rn(va.w);
        }
#pragma unroll
        for (int v = 0; v < 2; v++) {
            int g = tid + v * 256;
            int row = g / 32, c4 = g % 32;
            Bs[row][c4 * 2 + 0] = __floats2half2_rn(vb[v].x, vb[v].y);
            Bs[row][c4 * 2 + 1] = __floats2half2_rn(vb[v].z, vb[v].w);
        }
    };

    fetch(0);
    commit();
    __syncthreads();

    const __half2 hz = __floats2half2_rn(0.f, 0.f);
    for (int t = 0; t < HID / BK; t++) {
        if (t + 1 < HID / BK) fetch((t + 1) * BK);
        __half2 hacc[4][4];
#pragma unroll
        for (int i = 0; i < 4; i++)
#pragma unroll
            for (int jp = 0; jp < 4; jp++) hacc[i][jp] = hz;
#pragma unroll
        for (int kk = 0; kk < BK; kk++) {
            __half2 asp[4], bp[4];
            *(uint4*)asp = *(const uint4*)&As[kk][trow * 4];
            *(uint4*)bp  = *(const uint4*)&Bs[kk][tcol * 4];
#pragma unroll
            for (int i = 0; i < 4; i++)
#pragma unroll
                for (int jp = 0; jp < 4; jp++)
                    hacc[i][jp] = __hfma2(asp[i], bp[jp], hacc[i][jp]);
        }
#pragma unroll
        for (int i = 0; i < 4; i++)
#pragma unroll
            for (int jp = 0; jp < 4; jp++) {
                float2 f = __half22float2(hacc[i][jp]);
                acc[i][jp * 2 + 0] += f.x;
                acc[i][jp * 2 + 1] += f.y;
            }
        __syncthreads();
        if (t + 1 < HID / BK) {
            commit();
            __syncthreads();
        }
    }

#pragma unroll
    for (int i = 0; i < 4; i++) {
        int gr = rowBase + trow * 4 + i;
        if (gr >= NN) continue;
        float dscale = rsqrtf((float)g_deg[r][gr] + 1.0f);
#pragma unroll
        for (int jp = 0; jp < 4; jp++) {
            int gc = tcol * 8 + jp * 2;
            __half2 hv = __floats2half2_rn(acc[i][jp * 2] * dscale,
                                           acc[i][jp * 2 + 1] * dscale);
            *(__half2*)&g_hw[r][(size_t)gr * BN + gc] = hv;
        }
    }
}

// ---------------- CSR-build device bodies --------------------------------------
__device__ void count_body(const int* __restrict__ ei, int E, int bid, int nb) {
#pragma unroll
    for (int r = 0; r < NREL; r++) {
        const int* dst = ei + (size_t)(2 * r + 1) * E;
        for (int e = bid * 256 + (int)threadIdx.x; e < E; e += nb * 256) {
            int d = dst[e];
            if ((unsigned)d < NN) atomicAdd(&g_deg[r][d], 1);
        }
    }
}

__device__ void fill_body(const int* __restrict__ ei, int E, int bid, int nb) {
    const int nthreads = nb * 256;
    const int gtid = bid * 256 + (int)threadIdx.x;
    const int E4 = E >> 2;
#pragma unroll
    for (int r = 0; r < NREL; r++) {
        const int4* src4 = (const int4*)(ei + (size_t)(2 * r) * E);
        const int4* dst4 = (const int4*)(ei + (size_t)(2 * r + 1) * E);
        for (int i = gtid; i < E4; i += nthreads) {
            int4 s = src4[i];
            int4 d = dst4[i];
            int p0 = -1, p1 = -1, p2 = -1, p3 = -1;
            if ((unsigned)d.x < NN && (unsigned)s.x < NN) p0 = atomicAdd(&g_cur[r][d.x], 1);
            if ((unsigned)d.y < NN && (unsigned)s.y < NN) p1 = atomicAdd(&g_cur[r][d.y], 1);
            if ((unsigned)d.z < NN && (unsigned)s.z < NN) p2 = atomicAdd(&g_cur[r][d.z], 1);
            if ((unsigned)d.w < NN && (unsigned)s.w < NN) p3 = atomicAdd(&g_cur[r][d.w], 1);
            if (p0 >= 0) g_csr[r][p0] = s.x;
            if (p1 >= 0) g_csr[r][p1] = s.y;
            if (p2 >= 0) g_csr[r][p2] = s.z;
            if (p3 >= 0) g_csr[r][p3] = s.w;
        }
    }
}

__device__ void scan_body(int r) {
    __shared__ __align__(16) int wsum[8];
    __shared__ int carry;
    const int tid = threadIdx.x;
    const int lane = tid & 31;
    const int wid  = tid >> 5;
    if (tid == 0) carry = 0;
    __syncthreads();
    for (int base = 0; base < NN; base += 256) {
        int i = base + tid;
        int v = (i < NN) ? g_deg[r][i] : 0;
        int x = v;
#pragma unroll
        for (int o = 1; o < 32; o <<= 1) {
            int y = __shfl_up_sync(0xffffffffu, x, o);
            if (lane >= o) x += y;
        }
        if (lane == 31) wsum[wid] = x;
        __syncthreads();
        if (tid < 8) {
            int w = wsum[tid];
#pragma unroll
            for (int o = 1; o < 8; o <<= 1) {
                int y = __shfl_up_sync(0x000000ffu, w, o);
                if (tid >= o) w += y;
            }
            wsum[tid] = w;
        }
        __syncthreads();
        int excl = x - v + (wid > 0 ? wsum[wid - 1] : 0) + carry;
        if (i < NN) { g_off[r][i] = excl; g_cur[r][i] = excl; }
        int total = wsum[7];
        __syncthreads();
        if (tid == 0) carry += total;
        __syncthreads();
    }
    if (tid == 0) {
        g_off[r][NN] = carry;
        __threadfence();
        atomicAdd(&g_scan_done, 1);
    }
}

// ---------------- CSR gather body: warp per node, HADD2 chunks ----------------
// Writes g_h rows for its 8 nodes, then flags the completion counter.
__device__ __forceinline__ void gather_body(const float* __restrict__ bias,
                                            int gblk, int* done, int shift) {
    const int node = (gblk * 256 + (int)threadIdx.x) >> 5;
    const int lane = threadIdx.x & 31;
    const int c0 = lane * 4;

    if (node < NN) {
        float4 tot;
        tot.x = bias[c0 + 0] + bias[HID + c0 + 0] + bias[2 * HID + c0 + 0];
        tot.y = bias[c0 + 1] + bias[HID + c0 + 1] + bias[2 * HID + c0 + 1];
        tot.z = bias[c0 + 2] + bias[HID + c0 + 2] + bias[2 * HID + c0 + 2];
        tot.w = bias[c0 + 3] + bias[HID + c0 + 3] + bias[2 * HID + c0 + 3];

        const __half2 hz = __floats2half2_rn(0.f, 0.f);
#pragma unroll
        for (int r = 0; r < NREL; r++) {
            const __half* hwr = g_hw[r];
            float4 a;
            {
                uint2 raw = *(const uint2*)&hwr[(size_t)node * HID + c0];
                float2 f01 = __half22float2(*(__half2*)&raw.x);
                float2 f23 = __half22float2(*(__half2*)&raw.y);
                a.x = f01.x; a.y = f01.y; a.z = f23.x; a.w = f23.y;
            }
            const int beg = g_off[r][node];
            const int end = g_off[r][node + 1];
            const int* __restrict__ csr = g_csr[r];
            for (int t = beg; t < end; t += 32) {
                int idx = (t + lane < end) ? csr[t + lane] : 0;
                int n = end - t; if (n > 32) n = 32;
                __half2 ah0 = hz, ah1 = hz;
                for (int j = 0; j < n; j++) {
                    int s = __shfl_sync(0xffffffffu, idx, j);
                    uint2 raw = *(const uint2*)&hwr[(size_t)s * HID + c0];
                    ah0 = __hadd2(ah0, *(__half2*)&raw.x);
                    ah1 = __hadd2(ah1, *(__half2*)&raw.y);
                }
                float2 f01 = __half22float2(ah0);
                float2 f23 = __half22float2(ah1);
                a.x += f01.x; a.y += f01.y; a.z += f23.x; a.w += f23.y;
            }
            float dd = rsqrtf((float)g_deg[r][node] + 1.0f);
            tot.x += a.x * dd; tot.y += a.y * dd;
            tot.z += a.z * dd; tot.w += a.w * dd;
        }
        tot.x = fmaxf(tot.x, 0.f);
        tot.y = fmaxf(tot.y, 0.f);
        tot.z = fmaxf(tot.z, 0.f);
        tot.w = fmaxf(tot.w, 0.f);
        ((float4*)g_h)[(size_t)node * (HID / 4) + lane] = tot;
    }
    __syncthreads();
    if (threadIdx.x == 0) {
        __threadfence();                     // publish g_h rows before flagging
        atomicAdd(&done[gblk >> shift], 1);
    }
}

// ---------------- kernels -------------------------------------------------------
#define EMB_TILES 782   /* ceil(50000/64) */
#define HREL_TILES 782  /* ceil(50000/64), BM=64 half GEMM */
#define FIN_TILES 391   /* ceil(50000/128) */
#define CNT_BLKS  128
#define FILL_BLKS 592
#define K3_GEMM   (NREL * HREL_TILES)   /* 2346 */
#define GATHER_BLKS 6250                /* 50000 nodes / 8 per block */

__global__ void zero_deg_kernel() {
    int i = blockIdx.x * blockDim.x + threadIdx.x;
    if (i == 0) g_scan_done = 0;
    if (i < 782) g_done1[i] = 0;
    if (i < 391) g_done2[i] = 0;
    if (i < NREL * NN) ((int*)g_deg)[i] = 0;
}

// K2: degree count + embedder GEMM (fp32)
__global__ __launch_bounds__(256)
void k2_emb_count(const float* __restrict__ x, const float* __restrict__ emb_w,
                  const float* __restrict__ emb_b,
                  const int* __restrict__ ei, int E) {
    if (blockIdx.x < CNT_BLKS)
        count_body(ei, E, blockIdx.x, CNT_BLKS);
    else
        sgemm_body<64, 128, 20, 4, 8, 0>(x, emb_w, emb_b, nullptr, NN, 300,
                                         blockIdx.x - CNT_BLKS);
}

// K3: scan + layer-0 relation GEMMs (half2) + flag-gated CSR fill
__global__ __launch_bounds__(256)
void k3_rel_scan_fill(const float* __restrict__ w,
                      const int* __restrict__ ei, int E) {
    int b = blockIdx.x;
    if (b < NREL) {
        scan_body(b);
    } else if (b < NREL + K3_GEMM) {
        b -= NREL;
        hgemm_body(w, b / HREL_TILES, b % HREL_TILES);
    } else {
        if (threadIdx.x == 0)
            while (atomicAdd(&g_scan_done, 0) < NREL) { }
        __syncthreads();
        fill_body(ei, E, b - NREL - K3_GEMM, FILL_BLKS);
    }
}

// K5: gather-1 (blocks 0..6249, flag done1 per 64-node tile) +
//     layer-1 relation GEMMs gated per-tile on done1.
__global__ __launch_bounds__(256)
void k5_gather_rel(const float* __restrict__ b0, const float* __restrict__ w1) {
    int b = blockIdx.x;
    if (b < GATHER_BLKS) {
        gather_body(b0, b, g_done1, 3);
    } else {
        b -= GATHER_BLKS;
        int tile = b % HREL_TILES;
        if (threadIdx.x == 0) {
            int expect = GATHER_BLKS - tile * 8;
            if (expect > 8) expect = 8;
            while (atomicAdd(&g_done1[tile], 0) < expect) { }
        }
        __syncthreads();
        hgemm_body(w1, b / HREL_TILES, tile);
    }
}

// K6: gather-2 (flag done2 per 128-node tile) + final linear gated per-tile.
__global__ __launch_bounds__(256)
void k6_gather_fin(const float* __restrict__ b1, const float* __restrict__ lin_w,
                   const float* __restrict__ lin_b, float* __restrict__ out) {
    int b = blockIdx.x;
    if (b < GATHER_BLKS) {
        gather_body(b1, b, g_done2, 4);
    } else {
        int tile = b - GATHER_BLKS;
        if (threadIdx.x == 0) {
            int expect = GATHER_BLKS - tile * 16;
            if (expect > 16) expect = 16;
            while (atomicAdd(&g_done2[tile], 0) < expect) { }
        }
        __syncthreads();
        sgemm_body<128, 64, 16, 8, 4, 2>(nullptr, lin_w, lin_b, out, NN, HID, tile);
    }
}

// ---------------- launch ------------------------------------------------------
extern "C" void kernel_launch(void* const* d_in, const int* in_sizes, int n_in,
                              void* d_out, int out_size) {
    const float* x     = (const float*)d_in[0];
    const int*   ei    = (const int*)d_in[1];   // int32 (JAX x64 disabled)
    const float* emb_w = (const float*)d_in[2];
    const float* emb_b = (const float*)d_in[3];
    const float* w0    = (const float*)d_in[4];
    const float* b0    = (const float*)d_in[5];
    const float* w1    = (const float*)d_in[6];
    const float* b1    = (const float*)d_in[7];
    const float* lin_w = (const float*)d_in[8];
    const float* lin_b = (const float*)d_in[9];
    float* out = (float*)d_out;

    const int E = in_sizes[1] / (2 * NREL);

    // stage 1: zero degree counters + flags
    zero_deg_kernel<<<(NREL * NN + 255) / 256, 256>>>();

    // stage 2: degree count || embedder GEMM
    k2_emb_count<<<CNT_BLKS + EMB_TILES, 256>>>(x, emb_w, emb_b, ei, E);

    // stage 3: scan || layer-0 relation GEMMs (HFMA2) || CSR fill (gated tail)
    k3_rel_scan_fill<<<NREL + K3_GEMM + FILL_BLKS, 256>>>(w0, ei, E);

    // stage 4: layer-0 gather || layer-1 relation GEMMs (per-tile gated)
    k5_gather_rel<<<GATHER_BLKS + K3_GEMM, 256>>>(b0, w1);

    // stage 5: layer-1 gather || final linear (per-tile gated)
    k6_gather_fin<<<GATHER_BLKS + FIN_TILES, 256>>>(b1, lin_w, lin_b, out);
}